// round 13
// baseline (speedup 1.0000x reference)
#include <cuda_runtime.h>
#include <cuda_bf16.h>
#include <cstdint>

// Problem constants
#define B_ 256
#define H_ 512
#define C_ 64
#define NKNOTS 100
#define KTERMS 8

#define TPB 512
#define NROWG 8            // row groups (blockIdx.x)
#define RG_CTAS 16         // CTAs per row group (gridDim.y)

typedef __nv_bfloat16 bf16;

// ---------------- smem layout (dynamic, byte offsets) ----------------
#define SM_WHH 0u
#define SM_WHL 32768u
#define SM_WOH 65536u
#define SM_WOL 98304u
#define SM_WXH 131072u
#define SM_WXL 135168u
#define SM_A   139264u
#define SM_ALO 172032u     // SM_A + 32768
#define SM_RED 172032u     // reduction overlay (on SM_ALO, used post-compute)
#define SM_TOTAL 204800u

// ---------------- global scratch (activations only, bf16 hi/lo) ----------------
__device__ __align__(16) bf16 g_relu_hi[B_ * H_], g_relu_lo[B_ * H_];
__device__ __align__(16) bf16 g_u_hi[B_ * H_],    g_u_lo[B_ * H_];
__device__ __align__(16) bf16 g_curr_hi[B_ * H_], g_curr_lo[B_ * H_];

// per-row-group barriers, cacheline padded
__device__ unsigned g_rbar_count[NROWG * 32];
__device__ unsigned g_rbar_gen[NROWG * 32];

extern __shared__ char smem[];

// ---------------- helpers ----------------
__device__ __forceinline__ uint32_t smem_u32(const void* p) {
    uint32_t a;
    asm("{ .reg .u64 t; cvta.to.shared.u64 t, %1; cvt.u32.u64 %0, t; }"
        : "=r"(a) : "l"(p));
    return a;
}
__device__ __forceinline__ uint32_t swz(int row, int u) {
    return (uint32_t)(row * 128 + ((u ^ (row & 7)) << 4));
}

#define CP_ASYNC16(sa, gp)                                                   \
    asm volatile("cp.async.cg.shared.global [%0], [%1], 16;"                 \
                 :: "r"((uint32_t)(sa)), "l"(gp))
#define CP_COMMIT() asm volatile("cp.async.commit_group;" ::: "memory")
#define CP_WAIT0()  asm volatile("cp.async.wait_group 0;" ::: "memory")

#define LDSM_X4(r, a)                                                        \
    asm volatile("ldmatrix.sync.aligned.m8n8.x4.shared.b16 {%0,%1,%2,%3}, [%4];" \
                 : "=r"((r)[0]), "=r"((r)[1]), "=r"((r)[2]), "=r"((r)[3])    \
                 : "r"(a))
#define LDSM_X2(r, a)                                                        \
    asm volatile("ldmatrix.sync.aligned.m8n8.x2.shared.b16 {%0,%1}, [%2];"   \
                 : "=r"((r)[0]), "=r"((r)[1]) : "r"(a))
#define MMA_BF16(d, a, b)                                                    \
    asm volatile("mma.sync.aligned.m16n8k16.row.col.f32.bf16.bf16.f32 "      \
                 "{%0,%1,%2,%3}, {%4,%5,%6,%7}, {%8,%9}, {%0,%1,%2,%3};"     \
                 : "+f"((d)[0]), "+f"((d)[1]), "+f"((d)[2]), "+f"((d)[3])    \
                 : "r"((a)[0]), "r"((a)[1]), "r"((a)[2]), "r"((a)[3]),       \
                   "r"((b)[0]), "r"((b)[1]))

// per-half named barrier (ids 1,2), 256 threads each
__device__ __forceinline__ void barh(int half) {
    asm volatile("bar.sync %0, %1;" :: "r"(half + 1), "r"(256) : "memory");
}

// row-group barrier: the 16 CTAs sharing blockIdx.x
__device__ __forceinline__ void rbar(int rg, unsigned& gen) {
    __syncthreads();
    if (threadIdx.x == 0) {
        __threadfence();
        unsigned old = atomicAdd(&g_rbar_count[rg * 32], 1);
        if (old == RG_CTAS - 1) {
            g_rbar_count[rg * 32] = 0;
            __threadfence();
            atomicAdd(&g_rbar_gen[rg * 32], 1);
        } else {
            while (*((volatile unsigned*)&g_rbar_gen[rg * 32]) == gen) { }
        }
        __threadfence();
        gen++;
    }
    __syncthreads();
}

// 8 fp32 -> packed hi/lo bf16 uint4s
__device__ __forceinline__ void pack8(float4 v0, float4 v1, uint4& hv, uint4& lv) {
    float f[8] = {v0.x, v0.y, v0.z, v0.w, v1.x, v1.y, v1.z, v1.w};
    unsigned hb[8], lb[8];
#pragma unroll
    for (int i = 0; i < 8; ++i) {
        __nv_bfloat16 hh = __float2bfloat16(f[i]);
        hb[i] = (unsigned)__bfloat16_as_ushort(hh);
        lb[i] = (unsigned)__bfloat16_as_ushort(
            __float2bfloat16(f[i] - __bfloat162float(hh)));
    }
    hv = make_uint4(hb[0] | (hb[1] << 16), hb[2] | (hb[3] << 16),
                    hb[4] | (hb[5] << 16), hb[6] | (hb[7] << 16));
    lv = make_uint4(lb[0] | (lb[1] << 16), lb[2] | (lb[3] << 16),
                    lb[4] | (lb[5] << 16), lb[6] | (lb[7] << 16));
}

// convert one fp32 slice (rows row0..row0+31, width K) into hi/lo SW128 tiles
__device__ __forceinline__ void conv_slice(const float* __restrict__ src,
                                           uint32_t hi_off, uint32_t lo_off,
                                           int row0, int K) {
    const int tasks = (K >> 6) * 256;
    for (int t = threadIdx.x; t < tasks; t += TPB) {
        int c = t >> 8;
        int r = (t >> 3) & 31;
        int u = t & 7;
        const float* g = src + (size_t)(row0 + r) * K + c * 64 + u * 8;
        float4 v0 = __ldg((const float4*)g);
        float4 v1 = __ldg((const float4*)(g + 4));
        uint4 hv, lv;
        pack8(v0, v1, hv, lv);
        *(uint4*)(smem + hi_off + c * 4096u + swz(r, u)) = hv;
        *(uint4*)(smem + lo_off + c * 4096u + swz(r, u)) = lv;
    }
}

// store a pair (v0,v1) as hi/lo bf16x2 at element offset off (L2 path)
__device__ __forceinline__ void st_split_pair(bf16* hi, bf16* lo, size_t off,
                                              float v0, float v1) {
    bf16 h0 = __float2bfloat16(v0), h1 = __float2bfloat16(v1);
    unsigned uh = ((unsigned)__bfloat16_as_ushort(h1) << 16) |
                  (unsigned)__bfloat16_as_ushort(h0);
    bf16 l0 = __float2bfloat16(v0 - __bfloat162float(h0));
    bf16 l1 = __float2bfloat16(v1 - __bfloat162float(h1));
    unsigned ul = ((unsigned)__bfloat16_as_ushort(l1) << 16) |
                  (unsigned)__bfloat16_as_ushort(l0);
    __stcg((unsigned*)(hi + off), uh);
    __stcg((unsigned*)(lo + off), ul);
}

// ---------------------------------------------------------------------------
// Compute nch chunks (A already in smem at a_hi / a_hi+32768) into acc.
// Per warp: one m16n8 tile, 3-term split MMA.
// ---------------------------------------------------------------------------
template <int NCH>
__device__ __forceinline__ void gemm_chunks(uint32_t sb, uint32_t a_hi,
                                            uint32_t w_hi, uint32_t w_lo,
                                            float (&acc)[3][4],
                                            int lrow, int kh, int brow, int bsel) {
#pragma unroll
    for (int c = 0; c < NCH; ++c) {
        const uint32_t whc = sb + w_hi + c * 4096u;
        const uint32_t wlc = sb + w_lo + c * 4096u;
        const uint32_t ac = sb + a_hi + c * 4096u;
        uint32_t bh[4][2], bl[4][2];
#pragma unroll
        for (int ks = 0; ks < 4; ++ks) {
            const uint32_t boff = swz(brow, ks * 2 + bsel);
            LDSM_X2(bh[ks], whc + boff);
            LDSM_X2(bl[ks], wlc + boff);
        }
#pragma unroll
        for (int ks = 0; ks < 4; ++ks) {
            const uint32_t am = ac + swz(lrow, ks * 2 + kh);
            uint32_t ah[4], al[4];
            LDSM_X4(ah, am);
            LDSM_X4(al, am + 32768u);
            MMA_BF16(acc[0], ah, bh[ks]);
            MMA_BF16(acc[1], al, bh[ks]);
            MMA_BF16(acc[2], ah, bl[ks]);
        }
    }
}

// stage this half's 4 chunks of A from global hi/lo bf16 buffers
__device__ __forceinline__ void stage_half(const bf16* __restrict__ Ghi,
                                           const bf16* __restrict__ Glo,
                                           int bm, uint32_t sb, int half) {
    barh(half);  // own half's previous reads of these buffers complete
    const int t8 = threadIdx.x & 255;
    const int r = t8 >> 3, u = t8 & 7;
    const uint32_t d = swz(r, u);
    const bf16* gh = Ghi + (size_t)(bm + r) * H_ + (half * 4) * 64 + u * 8;
    const bf16* gl = Glo + (size_t)(bm + r) * H_ + (half * 4) * 64 + u * 8;
#pragma unroll
    for (int k = 0; k < 4; ++k) {
        const uint32_t cb = (uint32_t)(half * 4 + k) * 4096u;
        CP_ASYNC16(sb + SM_A + cb + d, gh + k * 64);
        CP_ASYNC16(sb + SM_ALO + cb + d, gl + k * 64);
    }
    CP_COMMIT();
    CP_WAIT0();
    barh(half);  // half's tile visible to half's warps
}

__device__ __forceinline__ float fin(const float (&a)[3][4], int i) {
    return (a[0][i] + a[1][i]) + a[2][i];
}

// K-half reduction: upper stores n sets of 12 floats, lower adds.
__device__ __forceinline__ void red_store12(const float (&x)[3][4], int slot,
                                            int nslots) {
    float4* p = (float4*)(smem + SM_RED +
                          (size_t)(threadIdx.x - 256) * (nslots * 48) + slot * 48);
    p[0] = make_float4(x[0][0], x[0][1], x[0][2], x[0][3]);
    p[1] = make_float4(x[1][0], x[1][1], x[1][2], x[1][3]);
    p[2] = make_float4(x[2][0], x[2][1], x[2][2], x[2][3]);
}
__device__ __forceinline__ void red_add12(float (&x)[3][4], int slot, int nslots) {
    const float4* p = (const float4*)(smem + SM_RED +
                          (size_t)threadIdx.x * (nslots * 48) + slot * 48);
#pragma unroll
    for (int t = 0; t < 3; ++t) {
        float4 v = p[t];
        x[t][0] += v.x; x[t][1] += v.y; x[t][2] += v.z; x[t][3] += v.w;
    }
}

// ---------------------------------------------------------------------------
__global__ void __launch_bounds__(TPB, 1) cde_kernel(
    const float* __restrict__ tptr, const float* __restrict__ tobs,
    const float* __restrict__ coeffs, const float* __restrict__ dcoeffs,
    const float* __restrict__ h, const float* __restrict__ wx,
    const float* __restrict__ wh, const float* __restrict__ wout,
    const float* __restrict__ b0, const float* __restrict__ b1,
    float* __restrict__ out) {
    const int tid = threadIdx.x;
    const int half = tid >> 8;
    const int w = tid >> 5, l = tid & 31;
    const int wl = w & 7;
    const int mt = wl >> 2, ng = wl & 3;
    const int gid = l >> 2;
    const int rg = blockIdx.x;
    const int bm = blockIdx.x * 32;
    const int bn = blockIdx.y * 32;
    const uint32_t sb = smem_u32(smem);
    const uint32_t HOFF = (uint32_t)half * 16384u;

    __shared__ int s_idx;
    __shared__ float s_dt;

    unsigned gen = 0;
    if (tid == 0) {
        gen = *((volatile unsigned*)&g_rbar_gen[rg * 32]);
        float tv = tptr[0];
        int idx = 0;
        for (int i = 0; i < NKNOTS; i++) idx += (tobs[i] <= tv) ? 1 : 0;
        idx = min(max(idx - 1, 0), NKNOTS - 2);
        s_idx = idx;
        s_dt = tv - tobs[idx];
    }

    // ---- Prologue: convert W slices + h into resident SMEM (no global prep) ----
    conv_slice(wh, SM_WHH, SM_WHL, bn, H_);
    conv_slice(wout, SM_WOH, SM_WOL, bn, H_);
    conv_slice(wx, SM_WXH, SM_WXL, bn, C_);
    conv_slice(h, SM_A, SM_ALO, bm, H_);   // A := h for GEMM1
    __syncthreads();

    const int lrow = mt * 16 + (l & 15), kh = l >> 4;
    const int brow = ng * 8 + (l & 7), bsel = (l >> 3) & 1;
    const int col0 = bn + ng * 8 + (l & 3) * 2;
    const float bc0 = b0[col0], bc1 = b0[col0 + 1];
    const float bz0 = b1[col0], bz1 = b1[col0 + 1];
    int rw[2];
    rw[0] = mt * 16 + gid;
    rw[1] = mt * 16 + 8 + gid;

    // ---- GEMM1: a += h@wh^T (each half its 4 K-chunks) ----
    float a[3][4] = {}, aw[3][4] = {};
    gemm_chunks<4>(sb, SM_A + HOFF, SM_WHH + HOFF, SM_WHL + HOFF, a,
                   lrow, kh, brow, bsel);

    // ---- spline x/xdot directly into A slots 0 (x, lower) / 1 (xd, upper) ----
    __syncthreads();  // all h reads done before overwrite
    {
        const int t8 = tid & 255;
        const int r = t8 >> 3, u = t8 & 7;
        const float* csrc = half ? dcoeffs : coeffs;
        const int idx = s_idx;
        const float dt = s_dt;
        size_t base = ((size_t)((bm + r) * (NKNOTS - 1) + idx)) * 4 * C_ + u * 8;
        float4 k0a = __ldg((const float4*)(csrc + base + 0 * C_));
        float4 k0b = __ldg((const float4*)(csrc + base + 0 * C_ + 4));
        float4 k1a = __ldg((const float4*)(csrc + base + 1 * C_));
        float4 k1b = __ldg((const float4*)(csrc + base + 1 * C_ + 4));
        float4 k2a = __ldg((const float4*)(csrc + base + 2 * C_));
        float4 k2b = __ldg((const float4*)(csrc + base + 2 * C_ + 4));
        float4 k3a = __ldg((const float4*)(csrc + base + 3 * C_));
        float4 k3b = __ldg((const float4*)(csrc + base + 3 * C_ + 4));
        float4 fa, fb;
        fa.x = k0a.x + dt * (k1a.x + dt * (k2a.x + dt * k3a.x));
        fa.y = k0a.y + dt * (k1a.y + dt * (k2a.y + dt * k3a.y));
        fa.z = k0a.z + dt * (k1a.z + dt * (k2a.z + dt * k3a.z));
        fa.w = k0a.w + dt * (k1a.w + dt * (k2a.w + dt * k3a.w));
        fb.x = k0b.x + dt * (k1b.x + dt * (k2b.x + dt * k3b.x));
        fb.y = k0b.y + dt * (k1b.y + dt * (k2b.y + dt * k3b.y));
        fb.z = k0b.z + dt * (k1b.z + dt * (k2b.z + dt * k3b.z));
        fb.w = k0b.w + dt * (k1b.w + dt * (k2b.w + dt * k3b.w));
        uint4 hv, lv;
        pack8(fa, fb, hv, lv);
        const uint32_t slot = (uint32_t)half * 4096u;
        *(uint4*)(smem + SM_A + slot + swz(r, u)) = hv;
        *(uint4*)(smem + SM_ALO + slot + swz(r, u)) = lv;
    }
    barh(half);
    // lower: a += x@wx^T (slot 0); upper: aw += xd@wx^T (slot 1)
    if (half == 0)
        gemm_chunks<1>(sb, SM_A, SM_WXH, SM_WXL, a, lrow, kh, brow, bsel);
    else
        gemm_chunks<1>(sb, SM_A + 4096u, SM_WXH, SM_WXL, aw, lrow, kh, brow, bsel);

    // ---- L1 reduce + epilogue ----
    __syncthreads();
    if (half) { red_store12(a, 0, 2); red_store12(aw, 1, 2); }
    __syncthreads();
    float sdr[4], sdt4[4], hd[4];
    if (!half) {
        red_add12(a, 0, 2);
        red_add12(aw, 1, 2);
#pragma unroll
        for (int p = 0; p < 2; ++p) {
            float v0 = fin(a, p * 2 + 0) + bc0;
            float v1 = fin(a, p * 2 + 1) + bc1;
            size_t off = (size_t)(bm + rw[p]) * H_ + col0;
            st_split_pair(g_relu_hi, g_relu_lo, off, fmaxf(v0, 0.f), fmaxf(v1, 0.f));
            float d0 = 1.0f / (1.0f + expf(-v0));
            float d1 = 1.0f / (1.0f + expf(-v1));
            sdr[p * 2] = d0;
            sdr[p * 2 + 1] = d1;
            st_split_pair(g_u_hi, g_u_lo, off,
                          d0 * fin(aw, p * 2), d1 * fin(aw, p * 2 + 1));
        }
    }
    rbar(rg, gen);

    // ---- Z: z = relu@wout^T ; q = u0@wout^T ----
    {
        float z[3][4] = {}, q[3][4] = {};
        stage_half(g_relu_hi, g_relu_lo, bm, sb, half);
        gemm_chunks<4>(sb, SM_A + HOFF, SM_WOH + HOFF, SM_WOL + HOFF, z,
                       lrow, kh, brow, bsel);
        stage_half(g_u_hi, g_u_lo, bm, sb, half);
        gemm_chunks<4>(sb, SM_A + HOFF, SM_WOH + HOFF, SM_WOL + HOFF, q,
                       lrow, kh, brow, bsel);
        __syncthreads();
        if (half) { red_store12(z, 0, 2); red_store12(q, 1, 2); }
        __syncthreads();
        if (!half) {
            red_add12(z, 0, 2);
            red_add12(q, 1, 2);
#pragma unroll
            for (int p = 0; p < 2; ++p) {
                float t0 = tanhf(fin(z, p * 2 + 0) + bz0);
                float t1 = tanhf(fin(z, p * 2 + 1) + bz1);
                float d0 = 1.0f - t0 * t0, d1 = 1.0f - t1 * t1;
                sdt4[p * 2] = d0;
                sdt4[p * 2 + 1] = d1;
                float v0 = d0 * fin(q, p * 2), v1 = d1 * fin(q, p * 2 + 1);
                hd[p * 2] = v0;
                hd[p * 2 + 1] = v1;
                size_t off = (size_t)(bm + rw[p]) * H_ + col0;
                st_split_pair(g_curr_hi, g_curr_lo, off, v0, v1);
            }
        }
    }
    rbar(rg, gen);

    // ---- 8 von-Neumann iterations ----
    for (int it = 0; it < KTERMS; ++it) {
        {   // u = drelu * (curr @ wh^T)
            float acc2[3][4] = {};
            stage_half(g_curr_hi, g_curr_lo, bm, sb, half);
            gemm_chunks<4>(sb, SM_A + HOFF, SM_WHH + HOFF, SM_WHL + HOFF, acc2,
                           lrow, kh, brow, bsel);
            __syncthreads();
            if (half) red_store12(acc2, 0, 1);
            __syncthreads();
            if (!half) {
                red_add12(acc2, 0, 1);
#pragma unroll
                for (int p = 0; p < 2; ++p) {
                    size_t off = (size_t)(bm + rw[p]) * H_ + col0;
                    st_split_pair(g_u_hi, g_u_lo, off,
                                  sdr[p * 2] * fin(acc2, p * 2),
                                  sdr[p * 2 + 1] * fin(acc2, p * 2 + 1));
                }
            }
        }
        rbar(rg, gen);
        {   // curr' = dtanh * (u @ wout^T); hdot += curr'
            float acc2[3][4] = {};
            stage_half(g_u_hi, g_u_lo, bm, sb, half);
            gemm_chunks<4>(sb, SM_A + HOFF, SM_WOH + HOFF, SM_WOL + HOFF, acc2,
                           lrow, kh, brow, bsel);
            __syncthreads();
            if (half) red_store12(acc2, 0, 1);
            __syncthreads();
            if (!half) {
                red_add12(acc2, 0, 1);
#pragma unroll
                for (int p = 0; p < 2; ++p) {
                    float v0 = sdt4[p * 2] * fin(acc2, p * 2);
                    float v1 = sdt4[p * 2 + 1] * fin(acc2, p * 2 + 1);
                    hd[p * 2] += v0;
                    hd[p * 2 + 1] += v1;
                    if (it < KTERMS - 1) {
                        size_t off = (size_t)(bm + rw[p]) * H_ + col0;
                        st_split_pair(g_curr_hi, g_curr_lo, off, v0, v1);
                    }
                }
            }
            if (it < KTERMS - 1) rbar(rg, gen);
        }
    }

    // ---- write h_dot (fp32, lower half) ----
    if (!half) {
#pragma unroll
        for (int p = 0; p < 2; ++p) {
            size_t off = (size_t)(bm + rw[p]) * H_ + col0;
            *(float2*)(out + off) = make_float2(hd[p * 2], hd[p * 2 + 1]);
        }
    }
}

// ---------------------------------------------------------------------------
extern "C" void kernel_launch(void* const* d_in, const int* in_sizes, int n_in,
                              void* d_out, int out_size) {
    const float* t      = (const float*)d_in[0];
    const float* h      = (const float*)d_in[1];
    const float* coeffs = (const float*)d_in[2];
    const float* dcoeff = (const float*)d_in[3];
    const float* tobs   = (const float*)d_in[4];
    const float* wx     = (const float*)d_in[5];
    const float* wh     = (const float*)d_in[6];
    const float* wout   = (const float*)d_in[7];
    const float* b0     = (const float*)d_in[8];
    const float* b1     = (const float*)d_in[9];
    float* out = (float*)d_out;

    cudaFuncSetAttribute(cde_kernel, cudaFuncAttributeMaxDynamicSharedMemorySize,
                         SM_TOTAL);
    dim3 grid(NROWG, RG_CTAS);  // 8 x 16 = 128 CTAs, single wave
    cde_kernel<<<grid, TPB, SM_TOTAL>>>(t, tobs, coeffs, dcoeff, h, wx, wh,
                                        wout, b0, b1, out);
}

// round 14
// speedup vs baseline: 1.0013x; 1.0013x over previous
#include <cuda_runtime.h>
#include <cuda_bf16.h>
#include <cstdint>

// Problem constants
#define B_ 256
#define H_ 512
#define C_ 64
#define NKNOTS 100
#define KTERMS 8

#define TPB 256
#define NROWG 8            // row groups (blockIdx.x)
#define RG_CTAS 16         // CTAs per row group (gridDim.y)

typedef __nv_bfloat16 bf16;

// ---------------- smem layout (dynamic, byte offsets) ----------------
#define SM_WHH 0u
#define SM_WHL 32768u
#define SM_WOH 65536u
#define SM_WOL 98304u
#define SM_WXH 131072u
#define SM_WXL 135168u
#define SM_A   139264u
#define SM_ALO 172032u     // SM_A + 32768
#define SM_TOTAL 204800u

// ---------------- global scratch (activations only, bf16 hi/lo) ----------------
__device__ __align__(16) bf16 g_relu_hi[B_ * H_], g_relu_lo[B_ * H_];
__device__ __align__(16) bf16 g_u_hi[B_ * H_],    g_u_lo[B_ * H_];
__device__ __align__(16) bf16 g_curr_hi[B_ * H_], g_curr_lo[B_ * H_];

// per-row-group barriers, cacheline padded
__device__ unsigned g_rbar_count[NROWG * 32];
__device__ unsigned g_rbar_gen[NROWG * 32];

extern __shared__ char smem[];

// ---------------- helpers ----------------
__device__ __forceinline__ uint32_t smem_u32(const void* p) {
    uint32_t a;
    asm("{ .reg .u64 t; cvta.to.shared.u64 t, %1; cvt.u32.u64 %0, t; }"
        : "=r"(a) : "l"(p));
    return a;
}
__device__ __forceinline__ uint32_t swz(int row, int u) {
    return (uint32_t)(row * 128 + ((u ^ (row & 7)) << 4));
}

#define CP_ASYNC16(sa, gp)                                                   \
    asm volatile("cp.async.cg.shared.global [%0], [%1], 16;"                 \
                 :: "r"((uint32_t)(sa)), "l"(gp))
#define CP_COMMIT() asm volatile("cp.async.commit_group;" ::: "memory")
#define CP_WAIT0()  asm volatile("cp.async.wait_group 0;" ::: "memory")
#define CP_WAIT1()  asm volatile("cp.async.wait_group 1;" ::: "memory")

#define LDSM_X4(r, a)                                                        \
    asm volatile("ldmatrix.sync.aligned.m8n8.x4.shared.b16 {%0,%1,%2,%3}, [%4];" \
                 : "=r"((r)[0]), "=r"((r)[1]), "=r"((r)[2]), "=r"((r)[3])    \
                 : "r"(a))
#define LDSM_X2(r, a)                                                        \
    asm volatile("ldmatrix.sync.aligned.m8n8.x2.shared.b16 {%0,%1}, [%2];"   \
                 : "=r"((r)[0]), "=r"((r)[1]) : "r"(a))
#define MMA_BF16(d, a, b)                                                    \
    asm volatile("mma.sync.aligned.m16n8k16.row.col.f32.bf16.bf16.f32 "      \
                 "{%0,%1,%2,%3}, {%4,%5,%6,%7}, {%8,%9}, {%0,%1,%2,%3};"     \
                 : "+f"((d)[0]), "+f"((d)[1]), "+f"((d)[2]), "+f"((d)[3])    \
                 : "r"((a)[0]), "r"((a)[1]), "r"((a)[2]), "r"((a)[3]),       \
                   "r"((b)[0]), "r"((b)[1]))

// row-group barrier: the 16 CTAs sharing blockIdx.x
__device__ __forceinline__ void rbar(int rg, unsigned& gen) {
    __syncthreads();
    if (threadIdx.x == 0) {
        __threadfence();
        unsigned old = atomicAdd(&g_rbar_count[rg * 32], 1);
        if (old == RG_CTAS - 1) {
            g_rbar_count[rg * 32] = 0;
            __threadfence();
            atomicAdd(&g_rbar_gen[rg * 32], 1);
        } else {
            while (*((volatile unsigned*)&g_rbar_gen[rg * 32]) == gen) { }
        }
        __threadfence();
        gen++;
    }
    __syncthreads();
}

// 8 fp32 -> packed hi/lo bf16 uint4s
__device__ __forceinline__ void pack8(float4 v0, float4 v1, uint4& hv, uint4& lv) {
    float f[8] = {v0.x, v0.y, v0.z, v0.w, v1.x, v1.y, v1.z, v1.w};
    unsigned hb[8], lb[8];
#pragma unroll
    for (int i = 0; i < 8; ++i) {
        __nv_bfloat16 hh = __float2bfloat16(f[i]);
        hb[i] = (unsigned)__bfloat16_as_ushort(hh);
        lb[i] = (unsigned)__bfloat16_as_ushort(
            __float2bfloat16(f[i] - __bfloat162float(hh)));
    }
    hv = make_uint4(hb[0] | (hb[1] << 16), hb[2] | (hb[3] << 16),
                    hb[4] | (hb[5] << 16), hb[6] | (hb[7] << 16));
    lv = make_uint4(lb[0] | (lb[1] << 16), lb[2] | (lb[3] << 16),
                    lb[4] | (lb[5] << 16), lb[6] | (lb[7] << 16));
}

// convert one fp32 slice (rows row0..row0+31, width K) into hi/lo SW128 tiles
__device__ __forceinline__ void conv_slice(const float* __restrict__ src,
                                           uint32_t hi_off, uint32_t lo_off,
                                           int row0, int K) {
    const int tasks = (K >> 6) * 256;
    for (int t = threadIdx.x; t < tasks; t += TPB) {
        int c = t >> 8;
        int r = (t >> 3) & 31;
        int u = t & 7;
        const float* g = src + (size_t)(row0 + r) * K + c * 64 + u * 8;
        float4 v0 = __ldg((const float4*)g);
        float4 v1 = __ldg((const float4*)(g + 4));
        uint4 hv, lv;
        pack8(v0, v1, hv, lv);
        *(uint4*)(smem + hi_off + c * 4096u + swz(r, u)) = hv;
        *(uint4*)(smem + lo_off + c * 4096u + swz(r, u)) = lv;
    }
}

// store a pair (v0,v1) as hi/lo bf16x2 at element offset off (L2 path)
__device__ __forceinline__ void st_split_pair(bf16* hi, bf16* lo, size_t off,
                                              float v0, float v1) {
    bf16 h0 = __float2bfloat16(v0), h1 = __float2bfloat16(v1);
    unsigned uh = ((unsigned)__bfloat16_as_ushort(h1) << 16) |
                  (unsigned)__bfloat16_as_ushort(h0);
    bf16 l0 = __float2bfloat16(v0 - __bfloat162float(h0));
    bf16 l1 = __float2bfloat16(v1 - __bfloat162float(h1));
    unsigned ul = ((unsigned)__bfloat16_as_ushort(l1) << 16) |
                  (unsigned)__bfloat16_as_ushort(l0);
    __stcg((unsigned*)(hi + off), uh);
    __stcg((unsigned*)(lo + off), ul);
}

// ---------------------------------------------------------------------------
// Compute NCH chunks (A already in smem at a_hi / a_hi+32768) into term-split
// acc: acc[0]+=Ahi*Whi, acc[1]+=Alo*Whi, acc[2]+=Ahi*Wlo.
// ---------------------------------------------------------------------------
template <int NCH>
__device__ __forceinline__ void gemm_chunks(uint32_t sb, uint32_t a_hi,
                                            uint32_t w_hi, uint32_t w_lo,
                                            float (&acc)[3][4],
                                            int lrow, int kh, int brow, int bsel) {
#pragma unroll
    for (int c = 0; c < NCH; ++c) {
        const uint32_t whc = sb + w_hi + c * 4096u;
        const uint32_t wlc = sb + w_lo + c * 4096u;
        const uint32_t ac = sb + a_hi + c * 4096u;
        uint32_t bh[4][2], bl[4][2];
#pragma unroll
        for (int ks = 0; ks < 4; ++ks) {
            const uint32_t boff = swz(brow, ks * 2 + bsel);
            LDSM_X2(bh[ks], whc + boff);
            LDSM_X2(bl[ks], wlc + boff);
        }
#pragma unroll
        for (int ks = 0; ks < 4; ++ks) {
            const uint32_t am = ac + swz(lrow, ks * 2 + kh);
            uint32_t ah[4], al[4];
            LDSM_X4(ah, am);
            LDSM_X4(al, am + 32768u);
            MMA_BF16(acc[0], ah, bh[ks]);
            MMA_BF16(acc[1], al, bh[ks]);
            MMA_BF16(acc[2], ah, bl[ks]);
        }
    }
}

// ---------------------------------------------------------------------------
// Staged 8-chunk GEMM (activations from global bf16 hi/lo): cp.async in two
// commit groups, compute first half while second lands. R12-identical.
// ---------------------------------------------------------------------------
__device__ __forceinline__ void gemmS(const bf16* __restrict__ Ahi,
                                      const bf16* __restrict__ Alo,
                                      int bm, uint32_t sb,
                                      uint32_t whi, uint32_t wlo,
                                      float (&acc)[3][4],
                                      int lrow, int kh, int brow, int bsel) {
    const int tid = threadIdx.x;
    const int fr = tid >> 3, fu = tid & 7;
    const uint32_t d_a = swz(fr, fu);
    const bf16* gh = Ahi + (size_t)(bm + fr) * H_ + fu * 8;
    const bf16* gl = Alo + (size_t)(bm + fr) * H_ + fu * 8;

    __syncthreads();  // previous reads of SM_A complete
#pragma unroll
    for (int c = 0; c < 4; ++c) {
        CP_ASYNC16(sb + SM_A + c * 4096u + d_a, gh + c * 64);
        CP_ASYNC16(sb + SM_ALO + c * 4096u + d_a, gl + c * 64);
    }
    CP_COMMIT();
#pragma unroll
    for (int c = 4; c < 8; ++c) {
        CP_ASYNC16(sb + SM_A + c * 4096u + d_a, gh + c * 64);
        CP_ASYNC16(sb + SM_ALO + c * 4096u + d_a, gl + c * 64);
    }
    CP_COMMIT();
    CP_WAIT1();
    __syncthreads();  // first half visible

    gemm_chunks<4>(sb, SM_A, whi, wlo, acc, lrow, kh, brow, bsel);
    CP_WAIT0();
    __syncthreads();  // second half visible
    gemm_chunks<4>(sb, SM_A + 16384u, whi + 16384u, wlo + 16384u, acc,
                   lrow, kh, brow, bsel);
}

__device__ __forceinline__ float fin(const float (&a)[3][4], int i) {
    return (a[0][i] + a[1][i]) + a[2][i];
}

// ---------------------------------------------------------------------------
__global__ void __launch_bounds__(TPB, 1) cde_kernel(
    const float* __restrict__ tptr, const float* __restrict__ tobs,
    const float* __restrict__ coeffs, const float* __restrict__ dcoeffs,
    const float* __restrict__ h, const float* __restrict__ wx,
    const float* __restrict__ wh, const float* __restrict__ wout,
    const float* __restrict__ b0, const float* __restrict__ b1,
    float* __restrict__ out) {
    const int tid = threadIdx.x;
    const int w = tid >> 5, l = tid & 31;
    const int mt = w >> 2, ng = w & 3;
    const int gid = l >> 2;
    const int rg = blockIdx.x;
    const int bm = blockIdx.x * 32;
    const int bn = blockIdx.y * 32;
    const uint32_t sb = smem_u32(smem);

    __shared__ int s_idx;
    __shared__ float s_dt;

    unsigned gen = 0;
    if (tid == 0) {
        gen = *((volatile unsigned*)&g_rbar_gen[rg * 32]);
        float tv = tptr[0];
        int idx = 0;
        for (int i = 0; i < NKNOTS; i++) idx += (tobs[i] <= tv) ? 1 : 0;
        idx = min(max(idx - 1, 0), NKNOTS - 2);
        s_idx = idx;
        s_dt = tv - tobs[idx];
    }

    const int col0 = bn + ng * 8 + (l & 3) * 2;
    const float bc0 = b0[col0], bc1 = b0[col0 + 1];
    const float bz0 = b1[col0], bz1 = b1[col0 + 1];
    const int lrow = mt * 16 + (l & 15), kh = l >> 4;
    const int brow = ng * 8 + (l & 7), bsel = (l >> 3) & 1;
    int rw[2];
    rw[0] = mt * 16 + gid;
    rw[1] = mt * 16 + 8 + gid;

    // ---- Prologue: in-CTA conversion of W slices + h (no global prep) ----
    conv_slice(wh, SM_WHH, SM_WHL, bn, H_);
    conv_slice(wout, SM_WOH, SM_WOL, bn, H_);
    conv_slice(wx, SM_WXH, SM_WXL, bn, C_);
    conv_slice(h, SM_A, SM_ALO, bm, H_);   // A := h rows bm..bm+31
    __syncthreads();

    float sdr[4], sdt4[4], hd[4];

    // ---- L1: a = h@wh^T + x@wx^T ; aw = xdot@wx^T ----
    {
        float a[3][4] = {}, aw[3][4] = {};
        gemm_chunks<8>(sb, SM_A, SM_WHH, SM_WHL, a, lrow, kh, brow, bsel);
        __syncthreads();  // h reads done before overwrite with spline values
        {   // spline: x -> A slot 0, xdot -> A slot 1 (hi+lo)
            const int r = tid >> 3, u = tid & 7;
            const int idx = s_idx;
            const float dt = s_dt;
            size_t base = ((size_t)((bm + r) * (NKNOTS - 1) + idx)) * 4 * C_ + u * 8;
#pragma unroll
            for (int which = 0; which < 2; ++which) {
                const float* csrc = which ? dcoeffs : coeffs;
                float4 k0a = __ldg((const float4*)(csrc + base + 0 * C_));
                float4 k0b = __ldg((const float4*)(csrc + base + 0 * C_ + 4));
                float4 k1a = __ldg((const float4*)(csrc + base + 1 * C_));
                float4 k1b = __ldg((const float4*)(csrc + base + 1 * C_ + 4));
                float4 k2a = __ldg((const float4*)(csrc + base + 2 * C_));
                float4 k2b = __ldg((const float4*)(csrc + base + 2 * C_ + 4));
                float4 k3a = __ldg((const float4*)(csrc + base + 3 * C_));
                float4 k3b = __ldg((const float4*)(csrc + base + 3 * C_ + 4));
                float4 fa, fb;
                fa.x = k0a.x + dt * (k1a.x + dt * (k2a.x + dt * k3a.x));
                fa.y = k0a.y + dt * (k1a.y + dt * (k2a.y + dt * k3a.y));
                fa.z = k0a.z + dt * (k1a.z + dt * (k2a.z + dt * k3a.z));
                fa.w = k0a.w + dt * (k1a.w + dt * (k2a.w + dt * k3a.w));
                fb.x = k0b.x + dt * (k1b.x + dt * (k2b.x + dt * k3b.x));
                fb.y = k0b.y + dt * (k1b.y + dt * (k2b.y + dt * k3b.y));
                fb.z = k0b.z + dt * (k1b.z + dt * (k2b.z + dt * k3b.z));
                fb.w = k0b.w + dt * (k1b.w + dt * (k2b.w + dt * k3b.w));
                uint4 hv, lv;
                pack8(fa, fb, hv, lv);
                const uint32_t slot = (uint32_t)which * 4096u;
                *(uint4*)(smem + SM_A + slot + swz(r, u)) = hv;
                *(uint4*)(smem + SM_ALO + slot + swz(r, u)) = lv;
            }
        }
        __syncthreads();
        gemm_chunks<1>(sb, SM_A, SM_WXH, SM_WXL, a, lrow, kh, brow, bsel);
        gemm_chunks<1>(sb, SM_A + 4096u, SM_WXH, SM_WXL, aw, lrow, kh, brow, bsel);
#pragma unroll
        for (int p = 0; p < 2; ++p) {
            float v0 = fin(a, p * 2 + 0) + bc0;
            float v1 = fin(a, p * 2 + 1) + bc1;
            size_t off = (size_t)(bm + rw[p]) * H_ + col0;
            st_split_pair(g_relu_hi, g_relu_lo, off, fmaxf(v0, 0.f), fmaxf(v1, 0.f));
            float d0 = 1.0f / (1.0f + expf(-v0));
            float d1 = 1.0f / (1.0f + expf(-v1));
            sdr[p * 2] = d0;
            sdr[p * 2 + 1] = d1;
            st_split_pair(g_u_hi, g_u_lo, off,
                          d0 * fin(aw, p * 2), d1 * fin(aw, p * 2 + 1));
        }
    }
    rbar(rg, gen);

    // ---- Z: z = relu@wout^T ; q = u0@wout^T ----
    {
        float z[3][4] = {}, q[3][4] = {};
        gemmS(g_relu_hi, g_relu_lo, bm, sb, SM_WOH, SM_WOL, z,
              lrow, kh, brow, bsel);
        gemmS(g_u_hi, g_u_lo, bm, sb, SM_WOH, SM_WOL, q,
              lrow, kh, brow, bsel);
#pragma unroll
        for (int p = 0; p < 2; ++p) {
            float t0 = tanhf(fin(z, p * 2 + 0) + bz0);
            float t1 = tanhf(fin(z, p * 2 + 1) + bz1);
            float d0 = 1.0f - t0 * t0, d1 = 1.0f - t1 * t1;
            sdt4[p * 2] = d0;
            sdt4[p * 2 + 1] = d1;
            float v0 = d0 * fin(q, p * 2), v1 = d1 * fin(q, p * 2 + 1);
            hd[p * 2] = v0;
            hd[p * 2 + 1] = v1;
            size_t off = (size_t)(bm + rw[p]) * H_ + col0;
            st_split_pair(g_curr_hi, g_curr_lo, off, v0, v1);
        }
    }
    rbar(rg, gen);

    // ---- 8 von-Neumann iterations ----
    for (int it = 0; it < KTERMS; ++it) {
        {   // u = drelu * (curr @ wh^T)
            float a[3][4] = {};
            gemmS(g_curr_hi, g_curr_lo, bm, sb, SM_WHH, SM_WHL, a,
                  lrow, kh, brow, bsel);
#pragma unroll
            for (int p = 0; p < 2; ++p) {
                size_t off = (size_t)(bm + rw[p]) * H_ + col0;
                st_split_pair(g_u_hi, g_u_lo, off,
                              sdr[p * 2] * fin(a, p * 2),
                              sdr[p * 2 + 1] * fin(a, p * 2 + 1));
            }
        }
        rbar(rg, gen);
        {   // curr' = dtanh * (u @ wout^T); hdot += curr'
            float c[3][4] = {};
            gemmS(g_u_hi, g_u_lo, bm, sb, SM_WOH, SM_WOL, c,
                  lrow, kh, brow, bsel);
#pragma unroll
            for (int p = 0; p < 2; ++p) {
                float v0 = sdt4[p * 2] * fin(c, p * 2);
                float v1 = sdt4[p * 2 + 1] * fin(c, p * 2 + 1);
                hd[p * 2] += v0;
                hd[p * 2 + 1] += v1;
                if (it < KTERMS - 1) {
                    size_t off = (size_t)(bm + rw[p]) * H_ + col0;
                    st_split_pair(g_curr_hi, g_curr_lo, off, v0, v1);
                }
            }
            if (it < KTERMS - 1) rbar(rg, gen);
        }
    }

    // ---- write h_dot (fp32) ----
#pragma unroll
    for (int p = 0; p < 2; ++p) {
        size_t off = (size_t)(bm + rw[p]) * H_ + col0;
        *(float2*)(out + off) = make_float2(hd[p * 2], hd[p * 2 + 1]);
    }
}

// ---------------------------------------------------------------------------
extern "C" void kernel_launch(void* const* d_in, const int* in_sizes, int n_in,
                              void* d_out, int out_size) {
    const float* t      = (const float*)d_in[0];
    const float* h      = (const float*)d_in[1];
    const float* coeffs = (const float*)d_in[2];
    const float* dcoeff = (const float*)d_in[3];
    const float* tobs   = (const float*)d_in[4];
    const float* wx     = (const float*)d_in[5];
    const float* wh     = (const float*)d_in[6];
    const float* wout   = (const float*)d_in[7];
    const float* b0     = (const float*)d_in[8];
    const float* b1     = (const float*)d_in[9];
    float* out = (float*)d_out;

    cudaFuncSetAttribute(cde_kernel, cudaFuncAttributeMaxDynamicSharedMemorySize,
                         SM_TOTAL);
    dim3 grid(NROWG, RG_CTAS);  // 8 x 16 = 128 CTAs, single wave
    cde_kernel<<<grid, TPB, SM_TOTAL>>>(t, tobs, coeffs, dcoeff, h, wx, wh,
                                        wout, b0, b1, out);
}

// round 16
// speedup vs baseline: 1.1181x; 1.1167x over previous
#include <cuda_runtime.h>
#include <cuda_bf16.h>
#include <cstdint>

// Problem constants
#define B_ 256
#define H_ 512
#define C_ 64
#define NKNOTS 100
#define KTERMS 8

#define TPB 256
#define NCTA 128
#define NROWG 8            // row groups (blockIdx.x)
#define RG_CTAS 16         // CTAs per row group (gridDim.y)
#define GTH (NCTA * TPB)

typedef __nv_bfloat16 bf16;

// ---------------- smem layout (dynamic, byte offsets) ----------------
#define SM_WHH 0u
#define SM_WHL 32768u
#define SM_WOH 65536u
#define SM_WOL 98304u
#define SM_WXH 131072u
#define SM_WXL 135168u
#define SM_A   139264u
#define SM_ALO 172032u     // SM_A + 32768
#define SM_TOTAL 204800u

// ---------------- global scratch (bf16 hi/lo splits) ----------------
__device__ __align__(16) bf16 g_h_hi[B_ * H_],  g_h_lo[B_ * H_];
__device__ __align__(16) bf16 g_x_hi[B_ * C_],  g_x_lo[B_ * C_];
__device__ __align__(16) bf16 g_xd_hi[B_ * C_], g_xd_lo[B_ * C_];
__device__ __align__(16) bf16 g_wh_hi[H_ * H_], g_wh_lo[H_ * H_];
__device__ __align__(16) bf16 g_wo_hi[H_ * H_], g_wo_lo[H_ * H_];
__device__ __align__(16) bf16 g_wx_hi[H_ * C_], g_wx_lo[H_ * C_];
__device__ __align__(16) bf16 g_relu_hi[B_ * H_], g_relu_lo[B_ * H_];
__device__ __align__(16) bf16 g_u_hi[B_ * H_],    g_u_lo[B_ * H_];
__device__ __align__(16) bf16 g_curr_hi[B_ * H_], g_curr_lo[B_ * H_];

// global barrier (prep only)
__device__ unsigned g_bar_count;
__device__ unsigned g_bar_gen;
// per-CTA monotonic produce flags, 128B padded
__device__ unsigned g_pflag[NROWG * RG_CTAS * 32];

extern __shared__ char smem[];

// ---------------- helpers ----------------
__device__ __forceinline__ uint32_t smem_u32(const void* p) {
    uint32_t a;
    asm("{ .reg .u64 t; cvta.to.shared.u64 t, %1; cvt.u32.u64 %0, t; }"
        : "=r"(a) : "l"(p));
    return a;
}
// SW128 swizzle on 128B rows
__device__ __forceinline__ uint32_t swz(int row, int u) {
    return (uint32_t)(row * 128 + ((u ^ (row & 7)) << 4));
}

#define CP_ASYNC16(sa, gp)                                                   \
    asm volatile("cp.async.cg.shared.global [%0], [%1], 16;"                 \
                 :: "r"((uint32_t)(sa)), "l"(gp))
#define CP_COMMIT() asm volatile("cp.async.commit_group;" ::: "memory")
#define CP_WAIT0()  asm volatile("cp.async.wait_group 0;" ::: "memory")
#define CP_WAIT1()  asm volatile("cp.async.wait_group 1;" ::: "memory")

#define LDSM_X4(r, a)                                                        \
    asm volatile("ldmatrix.sync.aligned.m8n8.x4.shared.b16 {%0,%1,%2,%3}, [%4];" \
                 : "=r"((r)[0]), "=r"((r)[1]), "=r"((r)[2]), "=r"((r)[3])    \
                 : "r"(a))
#define LDSM_X2(r, a)                                                        \
    asm volatile("ldmatrix.sync.aligned.m8n8.x2.shared.b16 {%0,%1}, [%2];"   \
                 : "=r"((r)[0]), "=r"((r)[1]) : "r"(a))
#define MMA_BF16(d, a, b)                                                    \
    asm volatile("mma.sync.aligned.m16n8k16.row.col.f32.bf16.bf16.f32 "      \
                 "{%0,%1,%2,%3}, {%4,%5,%6,%7}, {%8,%9}, {%0,%1,%2,%3};"     \
                 : "+f"((d)[0]), "+f"((d)[1]), "+f"((d)[2]), "+f"((d)[3])    \
                 : "r"((a)[0]), "r"((a)[1]), "r"((a)[2]), "r"((a)[3]),       \
                   "r"((b)[0]), "r"((b)[1]))

// global barrier (prep only; all 128 CTAs)
__device__ __forceinline__ void gbar(unsigned& gen) {
    __syncthreads();
    if (threadIdx.x == 0) {
        __threadfence();
        unsigned old = atomicAdd(&g_bar_count, 1);
        if (old == NCTA - 1) {
            g_bar_count = 0;
            __threadfence();
            atomicAdd(&g_bar_gen, 1);
        } else {
            while (*((volatile unsigned*)&g_bar_gen) == gen) { }
        }
        __threadfence();
        gen++;
    }
    __syncthreads();
}

// producer signal: all stores visible, then bump own flag
__device__ __forceinline__ void signal(int rg, int cy) {
    __threadfence();
    __syncthreads();
    if (threadIdx.x == 0)
        atomicAdd(&g_pflag[(rg * RG_CTAS + cy) * 32], 1u);
}

// wait until all 16 row-group flags reach tgt (warp-parallel poll; lanes 0..15)
__device__ __forceinline__ void wait_flags(int rg, unsigned tgt) {
    const int l = threadIdx.x & 31;
    if (l < RG_CTAS) {
        const unsigned* f = &g_pflag[(rg * RG_CTAS + l) * 32];
        unsigned v;
        do {
            asm volatile("ld.acquire.gpu.u32 %0, [%1];" : "=r"(v) : "l"(f));
        } while ((int)(v - tgt) < 0);
    }
    __syncwarp();
}

__device__ __forceinline__ void cvt_split(float v, bf16* hi, bf16* lo, int i) {
    bf16 h = __float2bfloat16(v);
    hi[i] = h;
    lo[i] = __float2bfloat16(v - __bfloat162float(h));
}

// store a pair (v0,v1) as hi/lo bf16x2 at element offset off (L2 path)
__device__ __forceinline__ void st_split_pair(bf16* hi, bf16* lo, size_t off,
                                              float v0, float v1) {
    bf16 h0 = __float2bfloat16(v0), h1 = __float2bfloat16(v1);
    unsigned uh = ((unsigned)__bfloat16_as_ushort(h1) << 16) |
                  (unsigned)__bfloat16_as_ushort(h0);
    bf16 l0 = __float2bfloat16(v0 - __bfloat162float(h0));
    bf16 l1 = __float2bfloat16(v1 - __bfloat162float(h1));
    unsigned ul = ((unsigned)__bfloat16_as_ushort(l1) << 16) |
                  (unsigned)__bfloat16_as_ushort(l0);
    __stcg((unsigned*)(hi + off), uh);
    __stcg((unsigned*)(lo + off), ul);
}

// ---------------------------------------------------------------------------
// NT GEMM partial with TERM-SPLIT accumulators (R12-identical):
//   acc[0] += Ahi*Whi, acc[1] += Alo*Whi, acc[2] += Ahi*Wlo
// A staged per GEMM via cp.async.cg in TWO commit groups.
// ---------------------------------------------------------------------------
template <int NCH>
__device__ __forceinline__ void gemmT(const bf16* __restrict__ Ahi,
                                      const bf16* __restrict__ Alo,
                                      int strideA, int bm, uint32_t sb,
                                      uint32_t whi, uint32_t wlo,
                                      float (&acc)[3][4]) {
    const int tid = threadIdx.x;
    const int w = tid >> 5, l = tid & 31;
    const int mt = w >> 2, ng = w & 3;
    const int fr = tid >> 3, fu = tid & 7;
    const uint32_t d_a = swz(fr, fu);
    const bf16* gh = Ahi + (size_t)(bm + fr) * strideA + fu * 8;
    const bf16* gl = Alo + (size_t)(bm + fr) * strideA + fu * 8;
    const int lrow = mt * 16 + (l & 15), kh = l >> 4;       // A
    const int brow = ng * 8 + (l & 7), bsel = (l >> 3) & 1; // B
    constexpr int H1 = (NCH > 1) ? NCH / 2 : NCH;           // first half size

    __syncthreads();  // previous GEMM's reads of SM_A complete
#pragma unroll
    for (int c = 0; c < H1; ++c) {
        CP_ASYNC16(sb + SM_A + c * 4096u + d_a, gh + c * 64);
        CP_ASYNC16(sb + SM_ALO + c * 4096u + d_a, gl + c * 64);
    }
    CP_COMMIT();
    if (NCH > 1) {
#pragma unroll
        for (int c = H1; c < NCH; ++c) {
            CP_ASYNC16(sb + SM_A + c * 4096u + d_a, gh + c * 64);
            CP_ASYNC16(sb + SM_ALO + c * 4096u + d_a, gl + c * 64);
        }
        CP_COMMIT();
        CP_WAIT1();   // first half (and any older groups, incl. W) done
    } else {
        CP_WAIT0();
    }
    __syncthreads();  // first half visible to all warps

#pragma unroll
    for (int c = 0; c < NCH; ++c) {
        if (NCH > 1 && c == H1) {
            CP_WAIT0();
            __syncthreads();  // second half visible
        }
        const uint32_t whc = sb + whi + c * 4096u;
        const uint32_t wlc = sb + wlo + c * 4096u;
        const uint32_t ac = sb + SM_A + c * 4096u;
        uint32_t bh[4][2], bl[4][2];
#pragma unroll
        for (int ks = 0; ks < 4; ++ks) {
            const uint32_t boff = swz(brow, ks * 2 + bsel);
            LDSM_X2(bh[ks], whc + boff);
            LDSM_X2(bl[ks], wlc + boff);
        }
#pragma unroll
        for (int ks = 0; ks < 4; ++ks) {
            const uint32_t am = ac + swz(lrow, ks * 2 + kh);
            uint32_t ah[4], al[4];
            LDSM_X4(ah, am);
            LDSM_X4(al, am + 32768u);   // SM_ALO - SM_A
            MMA_BF16(acc[0], ah, bh[ks]);
            MMA_BF16(acc[1], al, bh[ks]);
            MMA_BF16(acc[2], ah, bl[ks]);
        }
    }
}

__device__ __forceinline__ float fin(const float (&a)[3][4], int i) {
    return (a[0][i] + a[1][i]) + a[2][i];
}

// load one resident W slice (rows bn..bn+31, K as SW128 chunk tiles), cp.async
__device__ __forceinline__ void load_w(const bf16* __restrict__ src,
                                       uint32_t sb, uint32_t soff, int bn, int K) {
    const int tid = threadIdx.x;
    const int nu = (K / 64) * 32 * 8;
    for (int e = tid; e < nu; e += TPB) {
        int kc = e >> 8;
        int r = (e >> 3) & 31;
        int j = e & 7;
        CP_ASYNC16(sb + soff + kc * 4096 + swz(r, j),
                   src + (size_t)(bn + r) * K + kc * 64 + j * 8);
    }
}

// ---------------------------------------------------------------------------
__global__ void __launch_bounds__(TPB, 1) cde_kernel(
    const float* __restrict__ tptr, const float* __restrict__ tobs,
    const float* __restrict__ coeffs, const float* __restrict__ dcoeffs,
    const float* __restrict__ h, const float* __restrict__ wx,
    const float* __restrict__ wh, const float* __restrict__ wout,
    const float* __restrict__ b0, const float* __restrict__ b1,
    float* __restrict__ out) {
    const int tid = threadIdx.x;
    const int w = tid >> 5, l = tid & 31;
    const int mt = w >> 2, ng = w & 3;
    const int gid = l >> 2;
    const int rg = blockIdx.x;
    const int cy = blockIdx.y;
    const int bm = blockIdx.x * 32;
    const int bn = blockIdx.y * 32;
    const uint32_t sb = smem_u32(smem);

    __shared__ unsigned s_base;
    unsigned ggen = 0;
    if (tid == 0) {
        ggen = *((volatile unsigned*)&g_bar_gen);
        // own flag; equal across CTAs at launch start (17 bumps per launch each)
        s_base = *((volatile unsigned*)&g_pflag[(rg * RG_CTAS + cy) * 32]);
    }

    // ---- Phase -1: spline + fp32 -> bf16 hi/lo splits (grid-flat) ----
    {
        const int gt = (blockIdx.y * gridDim.x + blockIdx.x) * TPB + tid;
        float tv = tptr[0];
        int idx = 0;
        for (int i = 0; i < NKNOTS; i++) idx += (tobs[i] <= tv) ? 1 : 0;
        idx = min(max(idx - 1, 0), NKNOTS - 2);
        const float dt = tv - tobs[idx];
        for (int i = gt; i < B_ * C_; i += GTH) {
            int b = i / C_, c = i % C_;
            size_t base = ((size_t)(b * (NKNOTS - 1) + idx)) * 4 * C_ + c;
            float v = coeffs[base] + dt * (coeffs[base + C_] +
                      dt * (coeffs[base + 2 * C_] + dt * coeffs[base + 3 * C_]));
            cvt_split(v, g_x_hi, g_x_lo, i);
            v = dcoeffs[base] + dt * (dcoeffs[base + C_] +
                dt * (dcoeffs[base + 2 * C_] + dt * dcoeffs[base + 3 * C_]));
            cvt_split(v, g_xd_hi, g_xd_lo, i);
        }
        for (int i = gt; i < B_ * H_; i += GTH) cvt_split(h[i], g_h_hi, g_h_lo, i);
        for (int i = gt; i < H_ * H_; i += GTH) cvt_split(wh[i], g_wh_hi, g_wh_lo, i);
        for (int i = gt; i < H_ * H_; i += GTH) cvt_split(wout[i], g_wo_hi, g_wo_lo, i);
        for (int i = gt; i < H_ * C_; i += GTH) cvt_split(wx[i], g_wx_hi, g_wx_lo, i);
    }
    gbar(ggen);   // only global barrier (prep visibility); also publishes s_base

    // ---- resident W tiles for this CTA's 32 cols ----
    load_w(g_wh_hi, sb, SM_WHH, bn, H_);
    load_w(g_wh_lo, sb, SM_WHL, bn, H_);
    load_w(g_wo_hi, sb, SM_WOH, bn, H_);
    load_w(g_wo_lo, sb, SM_WOL, bn, H_);
    load_w(g_wx_hi, sb, SM_WXH, bn, C_);
    load_w(g_wx_lo, sb, SM_WXL, bn, C_);
    CP_COMMIT();  // drained by the first gemmT's wait before any ldsm

    const unsigned fbase = s_base;
    const int col0 = bn + ng * 8 + (l & 3) * 2;
    const float bc0 = b0[col0], bc1 = b0[col0 + 1];
    const float bz0 = b1[col0], bz1 = b1[col0 + 1];
    int rw[2];
    rw[0] = mt * 16 + gid;
    rw[1] = mt * 16 + 8 + gid;

    float sdr[4], sdt[4], hd[4];

    // ---- L1: acc = h@wh^T + x@wx^T ; aw = xdot@wx^T ----
    {
        float a[3][4] = {}, aw[3][4] = {};
        gemmT<8>(g_h_hi, g_h_lo, H_, bm, sb, SM_WHH, SM_WHL, a);
        gemmT<1>(g_x_hi, g_x_lo, C_, bm, sb, SM_WXH, SM_WXL, a);
        gemmT<1>(g_xd_hi, g_xd_lo, C_, bm, sb, SM_WXH, SM_WXL, aw);
#pragma unroll
        for (int p = 0; p < 2; ++p) {
            float v0 = fin(a, p * 2 + 0) + bc0;
            float v1 = fin(a, p * 2 + 1) + bc1;
            size_t off = (size_t)(bm + rw[p]) * H_ + col0;
            st_split_pair(g_relu_hi, g_relu_lo, off, fmaxf(v0, 0.f), fmaxf(v1, 0.f));
            float d0 = 1.0f / (1.0f + expf(-v0));
            float d1 = 1.0f / (1.0f + expf(-v1));
            sdr[p * 2] = d0;
            sdr[p * 2 + 1] = d1;
            st_split_pair(g_u_hi, g_u_lo, off,
                          d0 * fin(aw, p * 2), d1 * fin(aw, p * 2 + 1));
        }
    }
    signal(rg, cy);   // flag = base+1

    // ---- Z: z = relu@wout^T ; uq = u0@wout^T ----
    {
        wait_flags(rg, fbase + 1);
        float z[3][4] = {}, q[3][4] = {};
        gemmT<8>(g_relu_hi, g_relu_lo, H_, bm, sb, SM_WOH, SM_WOL, z);
        gemmT<8>(g_u_hi, g_u_lo, H_, bm, sb, SM_WOH, SM_WOL, q);
#pragma unroll
        for (int p = 0; p < 2; ++p) {
            float t0 = tanhf(fin(z, p * 2 + 0) + bz0);
            float t1 = tanhf(fin(z, p * 2 + 1) + bz1);
            float d0 = 1.0f - t0 * t0, d1 = 1.0f - t1 * t1;
            sdt[p * 2] = d0;
            sdt[p * 2 + 1] = d1;
            float v0 = d0 * fin(q, p * 2), v1 = d1 * fin(q, p * 2 + 1);
            hd[p * 2] = v0;
            hd[p * 2 + 1] = v1;
            size_t off = (size_t)(bm + rw[p]) * H_ + col0;
            st_split_pair(g_curr_hi, g_curr_lo, off, v0, v1);
        }
    }
    signal(rg, cy);   // flag = base+2

    // ---- 8 von-Neumann iterations ----
    for (int it = 0; it < KTERMS; ++it) {
        {   // u = drelu * (curr @ wh^T); curr produced at flag base+2+2it
            wait_flags(rg, fbase + 2 + 2 * it);
            float a[3][4] = {};
            gemmT<8>(g_curr_hi, g_curr_lo, H_, bm, sb, SM_WHH, SM_WHL, a);
#pragma unroll
            for (int p = 0; p < 2; ++p) {
                size_t off = (size_t)(bm + rw[p]) * H_ + col0;
                st_split_pair(g_u_hi, g_u_lo, off,
                              sdr[p * 2] * fin(a, p * 2),
                              sdr[p * 2 + 1] * fin(a, p * 2 + 1));
            }
        }
        signal(rg, cy);   // flag = base+3+2it
        {   // curr' = dtanh * (u @ wout^T); hdot += curr'
            wait_flags(rg, fbase + 3 + 2 * it);
            float c[3][4] = {};
            gemmT<8>(g_u_hi, g_u_lo, H_, bm, sb, SM_WOH, SM_WOL, c);
#pragma unroll
            for (int p = 0; p < 2; ++p) {
                float v0 = sdt[p * 2] * fin(c, p * 2);
                float v1 = sdt[p * 2 + 1] * fin(c, p * 2 + 1);
                hd[p * 2] += v0;
                hd[p * 2 + 1] += v1;
                if (it < KTERMS - 1) {
                    size_t off = (size_t)(bm + rw[p]) * H_ + col0;
                    st_split_pair(g_curr_hi, g_curr_lo, off, v0, v1);
                }
            }
            if (it < KTERMS - 1) signal(rg, cy);   // flag = base+4+2it
        }
    }

    // ---- write h_dot (fp32) ----
#pragma unroll
    for (int p = 0; p < 2; ++p) {
        size_t off = (size_t)(bm + rw[p]) * H_ + col0;
        *(float2*)(out + off) = make_float2(hd[p * 2], hd[p * 2 + 1]);
    }
}

// ---------------------------------------------------------------------------
extern "C" void kernel_launch(void* const* d_in, const int* in_sizes, int n_in,
                              void* d_out, int out_size) {
    const float* t      = (const float*)d_in[0];
    const float* h      = (const float*)d_in[1];
    const float* coeffs = (const float*)d_in[2];
    const float* dcoeff = (const float*)d_in[3];
    const float* tobs   = (const float*)d_in[4];
    const float* wx     = (const float*)d_in[5];
    const float* wh     = (const float*)d_in[6];
    const float* wout   = (const float*)d_in[7];
    const float* b0     = (const float*)d_in[8];
    const float* b1     = (const float*)d_in[9];
    float* out = (float*)d_out;

    cudaFuncSetAttribute(cde_kernel, cudaFuncAttributeMaxDynamicSharedMemorySize,
                         SM_TOTAL);
    dim3 grid(NROWG, RG_CTAS);  // 8 x 16 = 128 CTAs, single wave
    cde_kernel<<<grid, TPB, SM_TOTAL>>>(t, tobs, coeffs, dcoeff, h, wx, wh,
                                        wout, b0, b1, out);
}